// round 2
// baseline (speedup 1.0000x reference)
#include <cuda_runtime.h>

// IntraLoss: loss = (1/N) * sum_n || features[n] - center[labels[n]] ||_2
// N=32768, C=1000, D=512. features f32 [N,D], labels int32 [N] (JAX x64 off),
// center f32 [C,D].

#define NROWS 32768
#define NCLS  1000
#define DDIM  512

__global__ void zero_out_kernel(float* out) {
    if (threadIdx.x == 0) out[0] = 0.0f;
}

__global__ __launch_bounds__(256) void intra_loss_kernel(
    const float4* __restrict__ feats,    // [N, D/4]
    const int* __restrict__ labels,      // [N] int32
    const float4* __restrict__ center,   // [C, D/4]
    float* __restrict__ out)
{
    const int lane = threadIdx.x & 31;
    const int wib  = threadIdx.x >> 5;                 // warp in block (0..7)
    const int row  = (blockIdx.x << 3) + wib;          // one warp per row

    float dist = 0.0f;
    if (row < NROWS) {
        int lbl = labels[row];
        lbl = min(max(lbl, 0), NCLS - 1);              // safety clamp
        const float4* fr = feats  + (size_t)row * (DDIM / 4);
        const float4* cr = center + (size_t)lbl * (DDIM / 4);

        float acc = 0.0f;
        #pragma unroll
        for (int i = 0; i < 4; i++) {
            float4 a = fr[lane + i * 32];
            float4 b = __ldg(&cr[lane + i * 32]);
            float dx = a.x - b.x;
            float dy = a.y - b.y;
            float dz = a.z - b.z;
            float dw = a.w - b.w;
            acc = fmaf(dx, dx, acc);
            acc = fmaf(dy, dy, acc);
            acc = fmaf(dz, dz, acc);
            acc = fmaf(dw, dw, acc);
        }
        // warp reduction
        #pragma unroll
        for (int s = 16; s > 0; s >>= 1)
            acc += __shfl_xor_sync(0xffffffffu, acc, s);
        dist = sqrtf(acc);
    }

    __shared__ float smem[8];
    if (lane == 0) smem[wib] = dist;
    __syncthreads();

    if (threadIdx.x == 0) {
        float s = 0.0f;
        #pragma unroll
        for (int i = 0; i < 8; i++) s += smem[i];
        atomicAdd(out, s * (1.0f / (float)NROWS));
    }
}

extern "C" void kernel_launch(void* const* d_in, const int* in_sizes, int n_in,
                              void* d_out, int out_size)
{
    const float4* feats  = (const float4*)d_in[0];
    const int* labels    = (const int*)d_in[1];
    const float4* center = (const float4*)d_in[2];
    float* out           = (float*)d_out;

    zero_out_kernel<<<1, 32>>>(out);
    // 8 warps per block -> 8 rows per block; 32768/8 = 4096 blocks
    intra_loss_kernel<<<NROWS / 8, 256>>>(feats, labels, center, out);
}

// round 3
// speedup vs baseline: 1.1572x; 1.1572x over previous
#include <cuda_runtime.h>

// IntraLoss: loss = (1/N) * sum_n || features[n] - center[labels[n]] ||_2
// N=32768, C=1000, D=512. features f32 [N,D], labels int32 [N], center f32 [C,D].
//
// Layout: 1024 blocks x 256 threads (8 warps). Each warp handles 4 rows,
// 8 lanes per row. Single wave, single pass, no atomics.

#define NROWS 32768
#define NCLS  1000
#define DDIM  512
#define NBLK  1024

__device__ float g_partials[NBLK];

__global__ __launch_bounds__(256) void intra_loss_kernel(
    const float4* __restrict__ feats,    // [N, D/4]
    const int* __restrict__ labels,      // [N] int32
    const float4* __restrict__ center)   // [C, D/4]
{
    const int lane = threadIdx.x & 31;
    const int wib  = threadIdx.x >> 5;                       // 0..7
    const int warpG = (blockIdx.x << 3) + wib;               // 0..8191
    const int g    = lane >> 3;                              // group 0..3
    const int l    = lane & 7;                               // lane in group
    const int row  = (warpG << 2) + g;                       // 4 rows per warp

    int lbl = labels[row];
    lbl = min(max(lbl, 0), NCLS - 1);

    const float4* fr = feats  + (size_t)row * (DDIM / 4);
    const float4* cr = center + (size_t)lbl * (DDIM / 4);

    float acc = 0.0f;
    #pragma unroll
    for (int i = 0; i < 16; i++) {
        float4 a = fr[l + i * 8];
        float4 b = __ldg(&cr[l + i * 8]);
        float dx = a.x - b.x;
        float dy = a.y - b.y;
        float dz = a.z - b.z;
        float dw = a.w - b.w;
        acc = fmaf(dx, dx, acc);
        acc = fmaf(dy, dy, acc);
        acc = fmaf(dz, dz, acc);
        acc = fmaf(dw, dw, acc);
    }

    // reduce within 8-lane group (all 4 rows in parallel)
    acc += __shfl_xor_sync(0xffffffffu, acc, 1);
    acc += __shfl_xor_sync(0xffffffffu, acc, 2);
    acc += __shfl_xor_sync(0xffffffffu, acc, 4);

    // one sqrt per row (group leaders), zeros elsewhere
    float d = (l == 0) ? sqrtf(acc) : 0.0f;

    // sum the 4 row-distances across groups
    d += __shfl_xor_sync(0xffffffffu, d, 8);
    d += __shfl_xor_sync(0xffffffffu, d, 16);

    __shared__ float smem[8];
    if (lane == 0) smem[wib] = d;
    __syncthreads();

    if (threadIdx.x == 0) {
        float s = 0.0f;
        #pragma unroll
        for (int i = 0; i < 8; i++) s += smem[i];
        g_partials[blockIdx.x] = s;
    }
}

__global__ __launch_bounds__(1024) void final_reduce_kernel(float* __restrict__ out)
{
    const int tid  = threadIdx.x;
    const int lane = tid & 31;
    const int wib  = tid >> 5;   // 0..31

    float v = g_partials[tid];
    #pragma unroll
    for (int s = 16; s > 0; s >>= 1)
        v += __shfl_xor_sync(0xffffffffu, v, s);

    __shared__ float smem[32];
    if (lane == 0) smem[wib] = v;
    __syncthreads();

    if (wib == 0) {
        float w = smem[lane];
        #pragma unroll
        for (int s = 16; s > 0; s >>= 1)
            w += __shfl_xor_sync(0xffffffffu, w, s);
        if (lane == 0) out[0] = w * (1.0f / (float)NROWS);
    }
}

extern "C" void kernel_launch(void* const* d_in, const int* in_sizes, int n_in,
                              void* d_out, int out_size)
{
    const float4* feats  = (const float4*)d_in[0];
    const int* labels    = (const int*)d_in[1];
    const float4* center = (const float4*)d_in[2];
    float* out           = (float*)d_out;

    intra_loss_kernel<<<NBLK, 256>>>(feats, labels, center);
    final_reduce_kernel<<<1, 1024>>>(out);
}

// round 4
// speedup vs baseline: 1.1805x; 1.0201x over previous
#include <cuda_runtime.h>

// IntraLoss: loss = (1/N) * sum_n || features[n] - center[labels[n]] ||_2
// N=32768, C=1000, D=512. features f32 [N,D], labels int32 [N], center f32 [C,D].
//
// Single kernel: 1024 blocks x 256 threads (8 warps), one wave.
// Each warp handles 4 rows (8 lanes per row). Block partials -> device array;
// the last block to finish performs the final reduction (no 2nd launch).

#define NROWS 32768
#define NCLS  1000
#define DDIM  512
#define NBLK  1024

__device__ float g_partials[NBLK];
__device__ unsigned int g_counter = 0;

__global__ __launch_bounds__(256) void intra_loss_kernel(
    const float4* __restrict__ feats,    // [N, D/4]
    const int* __restrict__ labels,      // [N] int32
    const float4* __restrict__ center,   // [C, D/4]
    float* __restrict__ out)
{
    const int lane  = threadIdx.x & 31;
    const int wib   = threadIdx.x >> 5;                      // 0..7
    const int warpG = (blockIdx.x << 3) + wib;               // 0..8191
    const int g     = lane >> 3;                             // group 0..3
    const int l     = lane & 7;                              // lane in group
    const int row   = (warpG << 2) + g;                      // 4 rows per warp

    int lbl = labels[row];
    lbl = min(max(lbl, 0), NCLS - 1);

    const float4* fr = feats  + (size_t)row * (DDIM / 4);
    const float4* cr = center + (size_t)lbl * (DDIM / 4);

    float acc = 0.0f;
    #pragma unroll
    for (int i = 0; i < 16; i++) {
        float4 a = fr[l + i * 8];
        float4 b = __ldg(&cr[l + i * 8]);
        float dx = a.x - b.x;
        float dy = a.y - b.y;
        float dz = a.z - b.z;
        float dw = a.w - b.w;
        acc = fmaf(dx, dx, acc);
        acc = fmaf(dy, dy, acc);
        acc = fmaf(dz, dz, acc);
        acc = fmaf(dw, dw, acc);
    }

    // reduce within 8-lane group (all 4 rows in parallel)
    acc += __shfl_xor_sync(0xffffffffu, acc, 1);
    acc += __shfl_xor_sync(0xffffffffu, acc, 2);
    acc += __shfl_xor_sync(0xffffffffu, acc, 4);

    // one sqrt per row (group leaders), zeros elsewhere
    float d = (l == 0) ? sqrtf(acc) : 0.0f;

    // sum the 4 row-distances across groups
    d += __shfl_xor_sync(0xffffffffu, d, 8);
    d += __shfl_xor_sync(0xffffffffu, d, 16);

    __shared__ float smem[8];
    __shared__ bool is_last;
    if (lane == 0) smem[wib] = d;
    __syncthreads();

    if (threadIdx.x == 0) {
        float s = 0.0f;
        #pragma unroll
        for (int i = 0; i < 8; i++) s += smem[i];
        g_partials[blockIdx.x] = s;
        __threadfence();
        unsigned int old = atomicAdd(&g_counter, 1u);
        is_last = (old == NBLK - 1);
    }
    __syncthreads();

    if (is_last) {
        // 256 threads, each reads 4 partials (L2-hot)
        float v = 0.0f;
        #pragma unroll
        for (int i = 0; i < 4; i++)
            v += g_partials[threadIdx.x + i * 256];

        #pragma unroll
        for (int s = 16; s > 0; s >>= 1)
            v += __shfl_xor_sync(0xffffffffu, v, s);

        __shared__ float smem2[8];
        if (lane == 0) smem2[wib] = v;
        __syncthreads();

        if (threadIdx.x == 0) {
            float w = 0.0f;
            #pragma unroll
            for (int i = 0; i < 8; i++) w += smem2[i];
            out[0] = w * (1.0f / (float)NROWS);
            g_counter = 0;   // reset for next graph replay
        }
    }
}

extern "C" void kernel_launch(void* const* d_in, const int* in_sizes, int n_in,
                              void* d_out, int out_size)
{
    const float4* feats  = (const float4*)d_in[0];
    const int* labels    = (const int*)d_in[1];
    const float4* center = (const float4*)d_in[2];
    float* out           = (float*)d_out;

    intra_loss_kernel<<<NBLK, 256>>>(feats, labels, center, out);
}